// round 7
// baseline (speedup 1.0000x reference)
#include <cuda_runtime.h>
#include <math.h>
#include <stdint.h>

#define BSZ 4
#define SEQ 2048
#define HID 1024
#define NHD 16
#define DH  64
#define TOK (BSZ*SEQ)   // 8192

// Scratch. "*_r" hold tf32-pre-rounded f32 bit patterns. g_ln/g_wq/g_wo/g_cr
// and g_q/g_kr are additionally K-dim permuted within 8-groups:
// slot 2j holds col j, slot 2j+1 holds col j+4.
__device__ float g_q  [(size_t)TOK*HID];
__device__ float g_ln [(size_t)TOK*HID];
__device__ float g_kr [(size_t)TOK*HID];
__device__ float g_vr [(size_t)TOK*HID];
__device__ float g_cr [(size_t)TOK*HID];
__device__ float g_wq [(size_t)3*HID*HID];
__device__ float g_wo [(size_t)HID*HID];

// ===========================================================================
// helpers
// ===========================================================================
__device__ __forceinline__ uint32_t s2u(const void* p) {
    uint32_t a;
    asm("{ .reg .u64 t; cvta.to.shared.u64 t, %1; cvt.u32.u64 %0, t; }"
        : "=r"(a) : "l"(p));
    return a;
}
__device__ __forceinline__ uint32_t f2tf(float x) {
    uint32_t r;
    asm("cvt.rna.tf32.f32 %0, %1;" : "=r"(r) : "f"(x));
    return r;
}
__device__ __forceinline__ float f2tff(float x) { return __uint_as_float(f2tf(x)); }
__device__ __forceinline__ int perm8(int c) { return (c < 4) ? 2*c : 2*c - 7; }

// D += A*B, m16n8k8 tf32
__device__ __forceinline__ void mma_tf32(float* d, const uint32_t* a, const uint32_t* b) {
    asm volatile(
        "mma.sync.aligned.m16n8k8.row.col.f32.tf32.tf32.f32 "
        "{%0,%1,%2,%3}, {%4,%5,%6,%7}, {%8,%9}, {%0,%1,%2,%3};"
        : "+f"(d[0]), "+f"(d[1]), "+f"(d[2]), "+f"(d[3])
        : "r"(a[0]), "r"(a[1]), "r"(a[2]), "r"(a[3]), "r"(b[0]), "r"(b[1]));
}
#define CP_ASYNC16(dst, src) \
    asm volatile("cp.async.cg.shared.global [%0], [%1], 16;" :: "r"(dst), "l"(src))
#define CP_COMMIT() asm volatile("cp.async.commit_group;" ::: "memory")
#define CP_WAIT(n)  asm volatile("cp.async.wait_group %0;" :: "n"(n) : "memory")

// ===========================================================================
// Kernel 0: round weights to tf32 + K-permute (within-8 slots)
// ===========================================================================
__global__ __launch_bounds__(256) void round4_kernel(const float* __restrict__ src,
                                                     float* __restrict__ dst, int n4)
{
    int i = blockIdx.x * blockDim.x + threadIdx.x;
    if (i < n4) {
        float4 v = reinterpret_cast<const float4*>(src)[i];
        int cb = i * 4;
        int base = cb & ~7;
        int c8 = cb & 7;          // 0 or 4
        dst[base + perm8(c8 + 0)] = f2tff(v.x);
        dst[base + perm8(c8 + 1)] = f2tff(v.y);
        dst[base + perm8(c8 + 2)] = f2tff(v.z);
        dst[base + perm8(c8 + 3)] = f2tff(v.w);
    }
}

// ===========================================================================
// Kernel 1: LayerNorm -> g_ln (tf32-rounded, K-permuted)
// ===========================================================================
__global__ __launch_bounds__(256) void ln_kernel(const float* __restrict__ x,
                                                 const float* __restrict__ w,
                                                 const float* __restrict__ bb,
                                                 float* __restrict__ y)
{
    int row = blockIdx.x;
    int t = threadIdx.x;
    float4 v = reinterpret_cast<const float4*>(x + (size_t)row * HID)[t];
    float s = v.x + v.y + v.z + v.w;
    float q = v.x*v.x + v.y*v.y + v.z*v.z + v.w*v.w;
#pragma unroll
    for (int o = 16; o > 0; o >>= 1) {
        s += __shfl_xor_sync(0xffffffffu, s, o);
        q += __shfl_xor_sync(0xffffffffu, q, o);
    }
    __shared__ float ss[8], sq[8], smu, srs;
    if ((t & 31) == 0) { ss[t >> 5] = s; sq[t >> 5] = q; }
    __syncthreads();
    if (t == 0) {
        float S = 0.f, Q2 = 0.f;
#pragma unroll
        for (int i = 0; i < 8; i++) { S += ss[i]; Q2 += sq[i]; }
        float mu = S * (1.0f / HID);
        smu = mu;
        srs = rsqrtf(Q2 * (1.0f / HID) - mu * mu + 1e-12f);
    }
    __syncthreads();
    float mu = smu, rs = srs;
    float4 w4 = reinterpret_cast<const float4*>(w)[t];
    float4 b4 = reinterpret_cast<const float4*>(bb)[t];
    float o0 = f2tff((v.x - mu) * rs * w4.x + b4.x);
    float o1 = f2tff((v.y - mu) * rs * w4.y + b4.y);
    float o2 = f2tff((v.z - mu) * rs * w4.z + b4.z);
    float o3 = f2tff((v.w - mu) * rs * w4.w + b4.w);
    int cb = 4 * t, base = cb & ~7, c8 = cb & 7;
    float* yr = y + (size_t)row * HID + base;
    yr[perm8(c8 + 0)] = o0;
    yr[perm8(c8 + 1)] = o1;
    yr[perm8(c8 + 2)] = o2;
    yr[perm8(c8 + 3)] = o3;
}

// ===========================================================================
// Kernel 2/4: tf32 mma GEMM  C[M,N] = A[M,K] * W[N,K]^T  (A,W K-permuted)
//   128x128 CTA, 256 thr, 8 warps (4M x 2N), warp 32x64.
//   BK=32, 3-stage cp.async, ONE sync/iter, XOR(row&3) chunk swizzle (no pad),
//   float2 fragment loads (K-permuted slot pairs).
// ===========================================================================
#define GROWW 32                    // words per tile row (no pad)
#define GTILEW (128*GROWW)          // 4096 words
#define GSSZ   (2*GTILEW)           // 8192 words per stage (A+B)
#define GEMM_SMEM (3*GSSZ*4)        // 98304 B

template<int MODE>
__global__ __launch_bounds__(256, 2) void gemm_mma(
    const float* __restrict__ Ap, const float* __restrict__ W,
    const float* __restrict__ bias,
    float* __restrict__ outq,
    float* __restrict__ outk, float* __restrict__ outkr,
    float* __restrict__ outv, float* __restrict__ outvr,
    float* __restrict__ outp)
{
    extern __shared__ float smf[];
    const uint32_t smb = s2u(smf);

    const int tid = threadIdx.x;
    const int wid = tid >> 5, lane = tid & 31;
    const int g = lane >> 2, tig = lane & 3;
    const int wM = wid & 3, wN = wid >> 2;
    const int m0 = blockIdx.x * 128, n0 = blockIdx.y * 128;
    const int NT = HID / 32;   // 32

    float acc[2][8][4];
#pragma unroll
    for (int a = 0; a < 2; a++)
#pragma unroll
        for (int b = 0; b < 8; b++)
#pragma unroll
            for (int c = 0; c < 4; c++) acc[a][b][c] = 0.f;

    // ---- async loader: 2048 16B chunks (A:1024, B:1024), 8/thread, swizzled
    auto load_stage = [&](int s, int kt) {
        uint32_t base = smb + (uint32_t)s * GSSZ * 4;
#pragma unroll
        for (int j = 0; j < 8; j++) {
            int ci  = tid + j * 256;
            int tb  = ci >> 10;            // 0 = A, 1 = B
            int row = (ci >> 3) & 127;
            int c   = ci & 7;
            int cX  = c ^ (row & 3);       // low-2-bit XOR swizzle
            const float* src = (tb ? (W  + (size_t)(n0 + row) * HID)
                                   : (Ap + (size_t)(m0 + row) * HID)) + kt * 32 + c * 4;
            uint32_t dst = base + (uint32_t)(tb * GTILEW + row * GROWW + cX * 4) * 4;
            CP_ASYNC16(dst, src);
        }
    };

    load_stage(0, 0); CP_COMMIT();
    load_stage(1, 1); CP_COMMIT();

    for (int kt = 0; kt < NT; kt++) {
        CP_WAIT(1);
        __syncthreads();                        // tile kt visible; prev iter reads done
        if (kt + 2 < NT) load_stage((kt + 2) % 3, kt + 2);
        CP_COMMIT();

        const float* As = smf + (kt % 3) * GSSZ;
        const float* Bs = As + GTILEW;
        const int xg = g & 3;
        const int off = 2 * (tig & 1);
#pragma unroll
        for (int ks = 0; ks < 4; ks++) {
            const int wA = 4 * ((2 * ks + (tig >> 1)) ^ xg) + off;  // swizzled word
            uint32_t af[2][4], bf[8][2];
#pragma unroll
            for (int mt = 0; mt < 2; mt++) {
                int r = wM * 32 + mt * 16 + g;
                float2 v0 = *reinterpret_cast<const float2*>(&As[r * GROWW + wA]);
                float2 v1 = *reinterpret_cast<const float2*>(&As[(r + 8) * GROWW + wA]);
                af[mt][0] = __float_as_uint(v0.x);
                af[mt][1] = __float_as_uint(v1.x);
                af[mt][2] = __float_as_uint(v0.y);
                af[mt][3] = __float_as_uint(v1.y);
            }
#pragma unroll
            for (int nt = 0; nt < 8; nt++) {
                int n = wN * 64 + nt * 8 + g;
                float2 v = *reinterpret_cast<const float2*>(&Bs[n * GROWW + wA]);
                bf[nt][0] = __float_as_uint(v.x);
                bf[nt][1] = __float_as_uint(v.y);
            }
#pragma unroll
            for (int mt = 0; mt < 2; mt++)
#pragma unroll
                for (int nt = 0; nt < 8; nt++)
                    mma_tf32(acc[mt][nt], af[mt], bf[nt]);
        }
    }
    // NOTE: no trailing sync needed before epilogue (per-thread data in regs)

    // ---- epilogue
    const int s0 = perm8(2 * tig);       // slot of col 2*tig
    const int s1 = perm8(2 * tig + 1);
#pragma unroll
    for (int nt = 0; nt < 8; nt++) {
        int cb = n0 + wN * 64 + nt * 8 + 2 * tig;
        float2 bv = {0.f, 0.f};
        int seg = 0, col = cb;
        if (MODE == 0) {
            bv = *reinterpret_cast<const float2*>(bias + cb);
            seg = cb >> 10;
            col = cb & 1023;
        }
        int base8 = col - 2 * tig;       // 8-aligned col base
#pragma unroll
        for (int mt = 0; mt < 2; mt++) {
            int r = m0 + wM * 32 + mt * 16 + g;
#pragma unroll
            for (int hh = 0; hh < 2; hh++) {
                size_t roff = (size_t)(r + hh * 8) * HID;
                float2 v = {acc[mt][nt][2*hh+0] + bv.x, acc[mt][nt][2*hh+1] + bv.y};
                if (MODE == 0) {
                    if (seg == 0) {
                        outq[roff + base8 + s0] = f2tff(v.x);   // permuted d
                        outq[roff + base8 + s1] = f2tff(v.y);
                    } else if (seg == 1) {
                        *reinterpret_cast<float2*>(outk + roff + col) = v;
                        outkr[roff + base8 + s0] = f2tff(v.x);  // permuted d
                        outkr[roff + base8 + s1] = f2tff(v.y);
                    } else {
                        *reinterpret_cast<float2*>(outv + roff + col) = v;
                        float2 vr = {f2tff(v.x), f2tff(v.y)};
                        *reinterpret_cast<float2*>(outvr + roff + col) = vr;
                    }
                } else {
                    *reinterpret_cast<float2*>(outp + roff + col) = v;
                }
            }
        }
    }
}

// ===========================================================================
// Kernel 3: flash attention, tf32 mma, 2-stage cp.async KV pipeline, 2 CTAs/SM
//   Q/K d-permuted (float2 frags); K tile XOR-swizzled 64-word rows.
//   stage: Ks[64][64](sw) | Vs[64][72] | ms[64]  (x2) ; Ps[128][68]
// ===========================================================================
#define KROW 64
#define VSTR 72
#define PSTR 68
#define VOFF (64*KROW)                      // 4096
#define MOFF (VOFF + 64*VSTR)               // 8704
#define STGW (MOFF + 64)                    // 8768 words / stage
#define PS_OFF (2*STGW)                     // 17536
#define ATT_SMEM ((PS_OFF + 128*PSTR) * 4)  // 104,960 B

__global__ __launch_bounds__(256, 2) void attn_mma(
    const float* __restrict__ Qp, const float* __restrict__ Kp,
    const float* __restrict__ Vp, const float* __restrict__ mask,
    float* __restrict__ ctx, float* __restrict__ ctxr)
{
    extern __shared__ float smf[];
    float* Ps = smf + PS_OFF;
    const uint32_t smb = s2u(smf);

    const int tid = threadIdx.x;
    const int wid = tid >> 5, lane = tid & 31;
    const int g = lane >> 2, tig = lane & 3;
    const int q0 = blockIdx.x * 128;
    const int h  = blockIdx.y;
    const int b  = blockIdx.z;
    const int NT = SEQ / 64;   // 32

    const float* qbase = Qp + (size_t)b * SEQ * HID + h * DH;
    const float* kbase = Kp + (size_t)b * SEQ * HID + h * DH;
    const float* vbase = Vp + (size_t)b * SEQ * HID + h * DH;

    const float L2E = 1.4426950408889634f;
    const float SCL = 0.125f * L2E;

    // ---- KV tile issue: K 1024 chunks (swizzled) + V 1024 chunks, 8/thread
    auto issue_tile = [&](int nt) {
        int s = nt & 1;
        uint32_t base = smb + (uint32_t)s * STGW * 4;
        int n0 = nt * 64;
#pragma unroll
        for (int j = 0; j < 8; j++) {
            int ci  = tid + j * 256;
            int tb  = ci >> 10;               // 0 = K, 1 = V
            int row = (ci >> 4) & 63;
            int c   = ci & 15;
            const float* src = (tb ? vbase : kbase) + (size_t)(n0 + row) * HID + c * 4;
            uint32_t w = tb ? (uint32_t)(VOFF + row * VSTR + c * 4)
                            : (uint32_t)(row * KROW + (c ^ (row & 3)) * 4);
            CP_ASYNC16(base + w * 4, src);
        }
        if (tid < 16)
            CP_ASYNC16(base + (uint32_t)(MOFF + tid * 4) * 4,
                       mask + (size_t)b * SEQ + n0 + tid * 4);
    };

    issue_tile(0); CP_COMMIT();
    issue_tile(1); CP_COMMIT();

    // ---- stage Q tile (128x64, d-permuted data) into Ps, lift frags (float2)
#pragma unroll
    for (int j = 0; j < 8; j++) {
        int ci = tid + j * 256;
        int row = ci >> 4, c4 = ci & 15;
        float4 v = *reinterpret_cast<const float4*>(qbase + (size_t)(q0 + row) * HID + c4 * 4);
        *reinterpret_cast<float4*>(&Ps[row * PSTR + c4 * 4]) = v;
    }
    __syncthreads();
    uint32_t qf[8][4];
    const int pr = wid * 16;
#pragma unroll
    for (int kt = 0; kt < 8; kt++) {
        float2 v0 = *reinterpret_cast<const float2*>(&Ps[(pr + g)     * PSTR + kt * 8 + 2 * tig]);
        float2 v1 = *reinterpret_cast<const float2*>(&Ps[(pr + 8 + g) * PSTR + kt * 8 + 2 * tig]);
        qf[kt][0] = __float_as_uint(v0.x);
        qf[kt][1] = __float_as_uint(v1.x);
        qf[kt][2] = __float_as_uint(v0.y);
        qf[kt][3] = __float_as_uint(v1.y);
    }

    float m0r = -1e30f, m1r = -1e30f, l0 = 0.f, l1 = 0.f;
    float oacc[8][4];
#pragma unroll
    for (int i = 0; i < 8; i++)
#pragma unroll
        for (int j = 0; j < 4; j++) oacc[i][j] = 0.f;

    const int xg = g & 3;
    const int koff = 2 * (tig & 1);

    for (int nt = 0; nt < NT; nt++) {
        CP_WAIT(1);
        __syncthreads();                     // tile nt arrived (also covers Q staging)
        const float* Ks = smf + (nt & 1) * STGW;
        const float* Vs = Ks + VOFF;
        const float* Ms = Ks + MOFF;

        // ---- S = Q K^T  (d permuted in both; float2 B-frag loads, swizzled)
        float sf[8][4];
#pragma unroll
        for (int i = 0; i < 8; i++)
#pragma unroll
            for (int j = 0; j < 4; j++) sf[i][j] = 0.f;
#pragma unroll
        for (int kt = 0; kt < 8; kt++) {
            const int wK = 4 * ((2 * kt + (tig >> 1)) ^ xg) + koff;
#pragma unroll
            for (int sn = 0; sn < 8; sn++) {
                float2 kv = *reinterpret_cast<const float2*>(&Ks[(sn * 8 + g) * KROW + wK]);
                uint32_t kb[2] = {__float_as_uint(kv.x), __float_as_uint(kv.y)};
                mma_tf32(sf[sn], qf[kt], kb);
            }
        }

        // ---- online softmax (base-2 domain)
        float zmax0 = -1e30f, zmax1 = -1e30f;
#pragma unroll
        for (int sn = 0; sn < 8; sn++) {
            float mc0 = Ms[sn * 8 + 2 * tig]     * L2E;
            float mc1 = Ms[sn * 8 + 2 * tig + 1] * L2E;
            sf[sn][0] = sf[sn][0] * SCL + mc0;
            sf[sn][1] = sf[sn][1] * SCL + mc1;
            sf[sn][2] = sf[sn][2] * SCL + mc0;
            sf[sn][3] = sf[sn][3] * SCL + mc1;
            zmax0 = fmaxf(zmax0, fmaxf(sf[sn][0], sf[sn][1]));
            zmax1 = fmaxf(zmax1, fmaxf(sf[sn][2], sf[sn][3]));
        }
#pragma unroll
        for (int o2 = 1; o2 < 4; o2 <<= 1) {
            zmax0 = fmaxf(zmax0, __shfl_xor_sync(0xffffffffu, zmax0, o2));
            zmax1 = fmaxf(zmax1, __shfl_xor_sync(0xffffffffu, zmax1, o2));
        }
        float mn0 = fmaxf(m0r, zmax0), mn1 = fmaxf(m1r, zmax1);
        float al0 = exp2f(m0r - mn0), al1 = exp2f(m1r - mn1);
        m0r = mn0; m1r = mn1;

        float rs0 = 0.f, rs1 = 0.f;
#pragma unroll
        for (int sn = 0; sn < 8; sn++) {
            float p0 = exp2f(sf[sn][0] - mn0);
            float p1 = exp2f(sf[sn][1] - mn0);
            float p2 = exp2f(sf[sn][2] - mn1);
            float p3 = exp2f(sf[sn][3] - mn1);
            rs0 += p0 + p1; rs1 += p2 + p3;
            uint2 w0 = {f2tf(p0), f2tf(p1)};
            uint2 w1 = {f2tf(p2), f2tf(p3)};
            *reinterpret_cast<uint2*>(&Ps[(pr + g)     * PSTR + sn * 8 + 2 * tig]) = w0;
            *reinterpret_cast<uint2*>(&Ps[(pr + 8 + g) * PSTR + sn * 8 + 2 * tig]) = w1;
        }
#pragma unroll
        for (int o2 = 1; o2 < 4; o2 <<= 1) {
            rs0 += __shfl_xor_sync(0xffffffffu, rs0, o2);
            rs1 += __shfl_xor_sync(0xffffffffu, rs1, o2);
        }
        l0 = l0 * al0 + rs0;
        l1 = l1 * al1 + rs1;
#pragma unroll
        for (int dn = 0; dn < 8; dn++) {
            oacc[dn][0] *= al0; oacc[dn][1] *= al0;
            oacc[dn][2] *= al1; oacc[dn][3] *= al1;
        }
        __syncwarp();   // P stores visible within warp before A-frag reads

        // ---- O += P V
#pragma unroll
        for (int kt = 0; kt < 8; kt++) {
            uint32_t pa[4];
            pa[0] = __float_as_uint(Ps[(pr + g)     * PSTR + kt * 8 + tig]);
            pa[1] = __float_as_uint(Ps[(pr + 8 + g) * PSTR + kt * 8 + tig]);
            pa[2] = __float_as_uint(Ps[(pr + g)     * PSTR + kt * 8 + tig + 4]);
            pa[3] = __float_as_uint(Ps[(pr + 8 + g) * PSTR + kt * 8 + tig + 4]);
#pragma unroll
            for (int dn = 0; dn < 8; dn++) {
                uint32_t vb[2];
                vb[0] = __float_as_uint(Vs[(kt * 8 + tig)     * VSTR + dn * 8 + g]);
                vb[1] = __float_as_uint(Vs[(kt * 8 + tig + 4) * VSTR + dn * 8 + g]);
                mma_tf32(oacc[dn], pa, vb);
            }
        }
        __syncthreads();                     // all warps done with stage nt&1
        if (nt + 2 < NT) issue_tile(nt + 2);
        CP_COMMIT();
    }

    // ---- write context: exact to d_out; rounded+K-permuted copy for proj GEMM
    float inv0 = 1.0f / l0, inv1 = 1.0f / l1;
    int r0 = b * SEQ + q0 + wid * 16 + g;
    const int s0 = perm8(2 * tig), s1 = perm8(2 * tig + 1);
#pragma unroll
    for (int dn = 0; dn < 8; dn++) {
        int col = h * DH + dn * 8 + 2 * tig;
        int base8 = col - 2 * tig;
        float2 v0 = {oacc[dn][0] * inv0, oacc[dn][1] * inv0};
        float2 v1 = {oacc[dn][2] * inv1, oacc[dn][3] * inv1};
        *reinterpret_cast<float2*>(ctx + (size_t)r0 * HID + col)       = v0;
        *reinterpret_cast<float2*>(ctx + (size_t)(r0 + 8) * HID + col) = v1;
        ctxr[(size_t)r0 * HID + base8 + s0]       = f2tff(v0.x);
        ctxr[(size_t)r0 * HID + base8 + s1]       = f2tff(v0.y);
        ctxr[(size_t)(r0 + 8) * HID + base8 + s0] = f2tff(v1.x);
        ctxr[(size_t)(r0 + 8) * HID + base8 + s1] = f2tff(v1.y);
    }
}

// ===========================================================================
// Host side
// ===========================================================================
extern "C" void kernel_launch(void* const* d_in, const int* in_sizes, int n_in,
                              void* d_out, int out_size)
{
    const float* input = (const float*)d_in[0];
    const float* mask  = (const float*)d_in[1];
    const float* nw    = (const float*)d_in[2];
    const float* nb    = (const float*)d_in[3];
    const float* qkvw  = (const float*)d_in[4];
    const float* qkvb  = (const float*)d_in[5];
    const float* ow    = (const float*)d_in[6];

    float* out   = (float*)d_out;
    float* out_o = out;
    float* out_k = out + (size_t)TOK * HID;
    float* out_v = out + 2 * (size_t)TOK * HID;
    float* out_c = out + 3 * (size_t)TOK * HID;

    float *gq, *gln, *gkr, *gvr, *gcr, *gwq, *gwo;
    cudaGetSymbolAddress((void**)&gq,  g_q);
    cudaGetSymbolAddress((void**)&gln, g_ln);
    cudaGetSymbolAddress((void**)&gkr, g_kr);
    cudaGetSymbolAddress((void**)&gvr, g_vr);
    cudaGetSymbolAddress((void**)&gcr, g_cr);
    cudaGetSymbolAddress((void**)&gwq, g_wq);
    cudaGetSymbolAddress((void**)&gwo, g_wo);

    cudaFuncSetAttribute(gemm_mma<0>, cudaFuncAttributeMaxDynamicSharedMemorySize, GEMM_SMEM);
    cudaFuncSetAttribute(gemm_mma<1>, cudaFuncAttributeMaxDynamicSharedMemorySize, GEMM_SMEM);
    cudaFuncSetAttribute(attn_mma,    cudaFuncAttributeMaxDynamicSharedMemorySize, ATT_SMEM);

    round4_kernel<<<(3*HID*HID/4 + 255)/256, 256>>>(qkvw, gwq, 3*HID*HID/4);
    round4_kernel<<<(HID*HID/4 + 255)/256, 256>>>(ow, gwo, HID*HID/4);
    ln_kernel<<<TOK, 256>>>(input, nw, nb, gln);
    gemm_mma<0><<<dim3(TOK/128, 3*HID/128), 256, GEMM_SMEM>>>(
        gln, gwq, qkvb, gq, out_k, gkr, out_v, gvr, nullptr);
    attn_mma<<<dim3(SEQ/128, NHD, BSZ), 256, ATT_SMEM>>>(gq, gkr, gvr, mask, out_c, gcr);
    gemm_mma<1><<<dim3(TOK/128, HID/128), 256, GEMM_SMEM>>>(
        gcr, gwo, nullptr, nullptr, nullptr, nullptr, nullptr, nullptr, out_o);
}

// round 8
// speedup vs baseline: 1.1315x; 1.1315x over previous
#include <cuda_runtime.h>
#include <math.h>
#include <stdint.h>

#define BSZ 4
#define SEQ 2048
#define HID 1024
#define NHD 16
#define DH  64
#define TOK (BSZ*SEQ)   // 8192

// Scratch. "*_r" hold tf32-pre-rounded f32 bit patterns. g_ln/g_wq/g_wo/g_cr
// and g_q/g_kr are additionally K-dim permuted within 8-groups:
// slot 2j holds col j, slot 2j+1 holds col j+4.
__device__ float g_q  [(size_t)TOK*HID];
__device__ float g_ln [(size_t)TOK*HID];
__device__ float g_kr [(size_t)TOK*HID];
__device__ float g_vr [(size_t)TOK*HID];
__device__ float g_cr [(size_t)TOK*HID];
__device__ float g_wq [(size_t)3*HID*HID];
__device__ float g_wo [(size_t)HID*HID];

// ===========================================================================
// helpers
// ===========================================================================
__device__ __forceinline__ uint32_t s2u(const void* p) {
    uint32_t a;
    asm("{ .reg .u64 t; cvta.to.shared.u64 t, %1; cvt.u32.u64 %0, t; }"
        : "=r"(a) : "l"(p));
    return a;
}
__device__ __forceinline__ uint32_t f2tf(float x) {
    uint32_t r;
    asm("cvt.rna.tf32.f32 %0, %1;" : "=r"(r) : "f"(x));
    return r;
}
__device__ __forceinline__ float f2tff(float x) { return __uint_as_float(f2tf(x)); }
__device__ __forceinline__ int perm8(int c) { return (c < 4) ? 2*c : 2*c - 7; }

// D += A*B, m16n8k8 tf32
__device__ __forceinline__ void mma_tf32(float* d, const uint32_t* a, const uint32_t* b) {
    asm volatile(
        "mma.sync.aligned.m16n8k8.row.col.f32.tf32.tf32.f32 "
        "{%0,%1,%2,%3}, {%4,%5,%6,%7}, {%8,%9}, {%0,%1,%2,%3};"
        : "+f"(d[0]), "+f"(d[1]), "+f"(d[2]), "+f"(d[3])
        : "r"(a[0]), "r"(a[1]), "r"(a[2]), "r"(a[3]), "r"(b[0]), "r"(b[1]));
}
#define CP_ASYNC16(dst, src) \
    asm volatile("cp.async.cg.shared.global [%0], [%1], 16;" :: "r"(dst), "l"(src))
#define CP_COMMIT() asm volatile("cp.async.commit_group;" ::: "memory")
#define CP_WAIT(n)  asm volatile("cp.async.wait_group %0;" :: "n"(n) : "memory")

// ===========================================================================
// Kernel 0: round weights to tf32 + K-permute (within-8 slots)
// ===========================================================================
__global__ __launch_bounds__(256) void round4_kernel(const float* __restrict__ src,
                                                     float* __restrict__ dst, int n4)
{
    int i = blockIdx.x * blockDim.x + threadIdx.x;
    if (i < n4) {
        float4 v = reinterpret_cast<const float4*>(src)[i];
        int cb = i * 4;
        int base = cb & ~7;
        int c8 = cb & 7;          // 0 or 4
        dst[base + perm8(c8 + 0)] = f2tff(v.x);
        dst[base + perm8(c8 + 1)] = f2tff(v.y);
        dst[base + perm8(c8 + 2)] = f2tff(v.z);
        dst[base + perm8(c8 + 3)] = f2tff(v.w);
    }
}

// ===========================================================================
// Kernel 1: LayerNorm -> g_ln (tf32-rounded, K-permuted)
// ===========================================================================
__global__ __launch_bounds__(256) void ln_kernel(const float* __restrict__ x,
                                                 const float* __restrict__ w,
                                                 const float* __restrict__ bb,
                                                 float* __restrict__ y)
{
    int row = blockIdx.x;
    int t = threadIdx.x;
    float4 v = reinterpret_cast<const float4*>(x + (size_t)row * HID)[t];
    float s = v.x + v.y + v.z + v.w;
    float q = v.x*v.x + v.y*v.y + v.z*v.z + v.w*v.w;
#pragma unroll
    for (int o = 16; o > 0; o >>= 1) {
        s += __shfl_xor_sync(0xffffffffu, s, o);
        q += __shfl_xor_sync(0xffffffffu, q, o);
    }
    __shared__ float ss[8], sq[8], smu, srs;
    if ((t & 31) == 0) { ss[t >> 5] = s; sq[t >> 5] = q; }
    __syncthreads();
    if (t == 0) {
        float S = 0.f, Q2 = 0.f;
#pragma unroll
        for (int i = 0; i < 8; i++) { S += ss[i]; Q2 += sq[i]; }
        float mu = S * (1.0f / HID);
        smu = mu;
        srs = rsqrtf(Q2 * (1.0f / HID) - mu * mu + 1e-12f);
    }
    __syncthreads();
    float mu = smu, rs = srs;
    float4 w4 = reinterpret_cast<const float4*>(w)[t];
    float4 b4 = reinterpret_cast<const float4*>(bb)[t];
    float o0 = f2tff((v.x - mu) * rs * w4.x + b4.x);
    float o1 = f2tff((v.y - mu) * rs * w4.y + b4.y);
    float o2 = f2tff((v.z - mu) * rs * w4.z + b4.z);
    float o3 = f2tff((v.w - mu) * rs * w4.w + b4.w);
    int cb = 4 * t, base = cb & ~7, c8 = cb & 7;
    float* yr = y + (size_t)row * HID + base;
    yr[perm8(c8 + 0)] = o0;
    yr[perm8(c8 + 1)] = o1;
    yr[perm8(c8 + 2)] = o2;
    yr[perm8(c8 + 3)] = o3;
}

// ===========================================================================
// Kernel 2/4: tf32 mma GEMM  C[M,N] = A[M,K] * W[N,K]^T  (A,W K-permuted)
//   128x128 CTA, 256 thr, 8 warps (4M x 2N), warp 32x64.
//   BK=32, 2-stage cp.async (R6 flow), row stride 40 words (40 mod 32 = 8
//   -> conflict-free float2 fragment loads on K-permuted slot pairs).
// ===========================================================================
#define GROWW 40                    // words per tile row (8 pad)
#define GTILEW (128*GROWW)          // 5120 words
#define GSSZ   (2*GTILEW)           // 10240 words per stage (A+B)
#define GEMM_SMEM (2*GSSZ*4)        // 81920 B -> 2 CTAs/SM

template<int MODE>
__global__ __launch_bounds__(256, 2) void gemm_mma(
    const float* __restrict__ Ap, const float* __restrict__ W,
    const float* __restrict__ bias,
    float* __restrict__ outq,
    float* __restrict__ outk, float* __restrict__ outkr,
    float* __restrict__ outv, float* __restrict__ outvr,
    float* __restrict__ outp)
{
    extern __shared__ float smf[];
    const uint32_t smb = s2u(smf);

    const int tid = threadIdx.x;
    const int wid = tid >> 5, lane = tid & 31;
    const int g = lane >> 2, tig = lane & 3;
    const int wM = wid & 3, wN = wid >> 2;
    const int m0 = blockIdx.x * 128, n0 = blockIdx.y * 128;
    const int NT = HID / 32;   // 32

    float acc[2][8][4];
#pragma unroll
    for (int a = 0; a < 2; a++)
#pragma unroll
        for (int b = 0; b < 8; b++)
#pragma unroll
            for (int c = 0; c < 4; c++) acc[a][b][c] = 0.f;

    // ---- async loader: 2048 16B chunks (A:1024, B:1024), 8/thread
    auto load_stage = [&](int s, int kt) {
        uint32_t base = smb + (uint32_t)s * GSSZ * 4;
#pragma unroll
        for (int j = 0; j < 8; j++) {
            int ci  = tid + j * 256;
            int tb  = ci >> 10;            // 0 = A, 1 = B
            int row = (ci >> 3) & 127;
            int c   = ci & 7;
            const float* src = (tb ? (W  + (size_t)(n0 + row) * HID)
                                   : (Ap + (size_t)(m0 + row) * HID)) + kt * 32 + c * 4;
            uint32_t dst = base + (uint32_t)(tb * GTILEW + row * GROWW + c * 4) * 4;
            CP_ASYNC16(dst, src);
        }
    };

    load_stage(0, 0); CP_COMMIT();
    load_stage(1, 1); CP_COMMIT();

    for (int kt = 0; kt < NT; kt++) {
        CP_WAIT(1);
        __syncthreads();                      // stage kt&1 data visible
        const float* As = smf + (kt & 1) * GSSZ;
        const float* Bs = As + GTILEW;
#pragma unroll
        for (int ks = 0; ks < 4; ks++) {
            const int wA = 8 * ks + 2 * tig;  // K-permuted float2 slot
            uint32_t af[2][4], bf[8][2];
#pragma unroll
            for (int mt = 0; mt < 2; mt++) {
                int r = wM * 32 + mt * 16 + g;
                float2 v0 = *reinterpret_cast<const float2*>(&As[r * GROWW + wA]);
                float2 v1 = *reinterpret_cast<const float2*>(&As[(r + 8) * GROWW + wA]);
                af[mt][0] = __float_as_uint(v0.x);
                af[mt][1] = __float_as_uint(v1.x);
                af[mt][2] = __float_as_uint(v0.y);
                af[mt][3] = __float_as_uint(v1.y);
            }
#pragma unroll
            for (int nt = 0; nt < 8; nt++) {
                int n = wN * 64 + nt * 8 + g;
                float2 v = *reinterpret_cast<const float2*>(&Bs[n * GROWW + wA]);
                bf[nt][0] = __float_as_uint(v.x);
                bf[nt][1] = __float_as_uint(v.y);
            }
#pragma unroll
            for (int mt = 0; mt < 2; mt++)
#pragma unroll
                for (int nt = 0; nt < 8; nt++)
                    mma_tf32(acc[mt][nt], af[mt], bf[nt]);
        }
        __syncthreads();                      // all warps done reading stage kt&1
        if (kt + 2 < NT) load_stage(kt & 1, kt + 2);
        CP_COMMIT();
    }

    // ---- epilogue
    const int s0 = perm8(2 * tig);       // slot of col 2*tig
    const int s1 = perm8(2 * tig + 1);
#pragma unroll
    for (int nt = 0; nt < 8; nt++) {
        int cb = n0 + wN * 64 + nt * 8 + 2 * tig;
        float2 bv = {0.f, 0.f};
        int seg = 0, col = cb;
        if (MODE == 0) {
            bv = *reinterpret_cast<const float2*>(bias + cb);
            seg = cb >> 10;
            col = cb & 1023;
        }
        int base8 = col - 2 * tig;       // 8-aligned col base
#pragma unroll
        for (int mt = 0; mt < 2; mt++) {
            int r = m0 + wM * 32 + mt * 16 + g;
#pragma unroll
            for (int hh = 0; hh < 2; hh++) {
                size_t roff = (size_t)(r + hh * 8) * HID;
                float2 v = {acc[mt][nt][2*hh+0] + bv.x, acc[mt][nt][2*hh+1] + bv.y};
                if (MODE == 0) {
                    if (seg == 0) {
                        outq[roff + base8 + s0] = f2tff(v.x);   // permuted d
                        outq[roff + base8 + s1] = f2tff(v.y);
                    } else if (seg == 1) {
                        *reinterpret_cast<float2*>(outk + roff + col) = v;
                        outkr[roff + base8 + s0] = f2tff(v.x);  // permuted d
                        outkr[roff + base8 + s1] = f2tff(v.y);
                    } else {
                        *reinterpret_cast<float2*>(outv + roff + col) = v;
                        float2 vr = {f2tff(v.x), f2tff(v.y)};
                        *reinterpret_cast<float2*>(outvr + roff + col) = vr;
                    }
                } else {
                    *reinterpret_cast<float2*>(outp + roff + col) = v;
                }
            }
        }
    }
}

// ===========================================================================
// Kernel 3: flash attention, tf32 mma, 2-stage cp.async KV pipeline.
//   Q/K d-permuted -> float2 K/Q fragment loads; K stride 72 (72 mod 32 = 8,
//   conflict-free). V scalar loads (already CF at stride 72). P stride 68.
//   256 thr (8 warps x 16 q-rows), q-tile 128, kv-tile 64, 1 CTA/SM.
// ===========================================================================
#define KSTR 72
#define VSTR 72
#define PSTR 68
#define VOFF (64*KSTR)                      // 4608
#define MOFF (VOFF + 64*VSTR)               // 9216
#define STGW (MOFF + 64)                    // 9280 words / stage
#define PS_OFF (2*STGW)                     // 18560
#define ATT_SMEM ((PS_OFF + 128*PSTR) * 4)  // 109,056 B

__global__ __launch_bounds__(256) void attn_mma(
    const float* __restrict__ Qp, const float* __restrict__ Kp,
    const float* __restrict__ Vp, const float* __restrict__ mask,
    float* __restrict__ ctx, float* __restrict__ ctxr)
{
    extern __shared__ float smf[];
    float* Ps = smf + PS_OFF;
    const uint32_t smb = s2u(smf);

    const int tid = threadIdx.x;
    const int wid = tid >> 5, lane = tid & 31;
    const int g = lane >> 2, tig = lane & 3;
    const int q0 = blockIdx.x * 128;
    const int h  = blockIdx.y;
    const int b  = blockIdx.z;
    const int NT = SEQ / 64;   // 32

    const float* qbase = Qp + (size_t)b * SEQ * HID + h * DH;
    const float* kbase = Kp + (size_t)b * SEQ * HID + h * DH;
    const float* vbase = Vp + (size_t)b * SEQ * HID + h * DH;

    const float L2E = 1.4426950408889634f;
    const float SCL = 0.125f * L2E;

    // ---- KV tile issue: K 1024 + V 1024 chunks, 8/thread; mask 16
    auto issue_tile = [&](int nt) {
        int s = nt & 1;
        uint32_t base = smb + (uint32_t)s * STGW * 4;
        int n0 = nt * 64;
#pragma unroll
        for (int j = 0; j < 8; j++) {
            int ci  = tid + j * 256;
            int tb  = ci >> 10;               // 0 = K, 1 = V
            int row = (ci >> 4) & 63;
            int c   = ci & 15;
            const float* src = (tb ? vbase : kbase) + (size_t)(n0 + row) * HID + c * 4;
            uint32_t w = tb ? (uint32_t)(VOFF + row * VSTR + c * 4)
                            : (uint32_t)(row * KSTR + c * 4);
            CP_ASYNC16(base + w * 4, src);
        }
        if (tid < 16)
            CP_ASYNC16(base + (uint32_t)(MOFF + tid * 4) * 4,
                       mask + (size_t)b * SEQ + n0 + tid * 4);
    };

    issue_tile(0); CP_COMMIT();
    issue_tile(1); CP_COMMIT();

    // ---- stage Q tile (128x64, d-permuted data) into Ps, lift frags (float2)
#pragma unroll
    for (int j = 0; j < 8; j++) {
        int ci = tid + j * 256;
        int row = ci >> 4, c4 = ci & 15;
        float4 v = *reinterpret_cast<const float4*>(qbase + (size_t)(q0 + row) * HID + c4 * 4);
        *reinterpret_cast<float4*>(&Ps[row * PSTR + c4 * 4]) = v;
    }
    __syncthreads();
    uint32_t qf[8][4];
    const int pr = wid * 16;
#pragma unroll
    for (int kt = 0; kt < 8; kt++) {
        float2 v0 = *reinterpret_cast<const float2*>(&Ps[(pr + g)     * PSTR + kt * 8 + 2 * tig]);
        float2 v1 = *reinterpret_cast<const float2*>(&Ps[(pr + 8 + g) * PSTR + kt * 8 + 2 * tig]);
        qf[kt][0] = __float_as_uint(v0.x);
        qf[kt][1] = __float_as_uint(v1.x);
        qf[kt][2] = __float_as_uint(v0.y);
        qf[kt][3] = __float_as_uint(v1.y);
    }

    float m0r = -1e30f, m1r = -1e30f, l0 = 0.f, l1 = 0.f;
    float oacc[8][4];
#pragma unroll
    for (int i = 0; i < 8; i++)
#pragma unroll
        for (int j = 0; j < 4; j++) oacc[i][j] = 0.f;

    for (int nt = 0; nt < NT; nt++) {
        CP_WAIT(1);
        __syncthreads();                     // tile nt arrived (also covers Q staging)
        const float* Ks = smf + (nt & 1) * STGW;
        const float* Vs = Ks + VOFF;
        const float* Ms = Ks + MOFF;

        // ---- S = Q K^T  (d permuted in both; conflict-free float2 B-frags)
        float sf[8][4];
#pragma unroll
        for (int i = 0; i < 8; i++)
#pragma unroll
            for (int j = 0; j < 4; j++) sf[i][j] = 0.f;
#pragma unroll
        for (int kt = 0; kt < 8; kt++) {
            const int wK = kt * 8 + 2 * tig;
#pragma unroll
            for (int sn = 0; sn < 8; sn++) {
                float2 kv = *reinterpret_cast<const float2*>(&Ks[(sn * 8 + g) * KSTR + wK]);
                uint32_t kb[2] = {__float_as_uint(kv.x), __float_as_uint(kv.y)};
                mma_tf32(sf[sn], qf[kt], kb);
            }
        }

        // ---- online softmax (base-2 domain)
        float zmax0 = -1e30f, zmax1 = -1e30f;
#pragma unroll
        for (int sn = 0; sn < 8; sn++) {
            float mc0 = Ms[sn * 8 + 2 * tig]     * L2E;
            float mc1 = Ms[sn * 8 + 2 * tig + 1] * L2E;
            sf[sn][0] = sf[sn][0] * SCL + mc0;
            sf[sn][1] = sf[sn][1] * SCL + mc1;
            sf[sn][2] = sf[sn][2] * SCL + mc0;
            sf[sn][3] = sf[sn][3] * SCL + mc1;
            zmax0 = fmaxf(zmax0, fmaxf(sf[sn][0], sf[sn][1]));
            zmax1 = fmaxf(zmax1, fmaxf(sf[sn][2], sf[sn][3]));
        }
#pragma unroll
        for (int o2 = 1; o2 < 4; o2 <<= 1) {
            zmax0 = fmaxf(zmax0, __shfl_xor_sync(0xffffffffu, zmax0, o2));
            zmax1 = fmaxf(zmax1, __shfl_xor_sync(0xffffffffu, zmax1, o2));
        }
        float mn0 = fmaxf(m0r, zmax0), mn1 = fmaxf(m1r, zmax1);
        float al0 = exp2f(m0r - mn0), al1 = exp2f(m1r - mn1);
        m0r = mn0; m1r = mn1;

        float rs0 = 0.f, rs1 = 0.f;
#pragma unroll
        for (int sn = 0; sn < 8; sn++) {
            float p0 = exp2f(sf[sn][0] - mn0);
            float p1 = exp2f(sf[sn][1] - mn0);
            float p2 = exp2f(sf[sn][2] - mn1);
            float p3 = exp2f(sf[sn][3] - mn1);
            rs0 += p0 + p1; rs1 += p2 + p3;
            uint2 w0 = {f2tf(p0), f2tf(p1)};
            uint2 w1 = {f2tf(p2), f2tf(p3)};
            *reinterpret_cast<uint2*>(&Ps[(pr + g)     * PSTR + sn * 8 + 2 * tig]) = w0;
            *reinterpret_cast<uint2*>(&Ps[(pr + 8 + g) * PSTR + sn * 8 + 2 * tig]) = w1;
        }
#pragma unroll
        for (int o2 = 1; o2 < 4; o2 <<= 1) {
            rs0 += __shfl_xor_sync(0xffffffffu, rs0, o2);
            rs1 += __shfl_xor_sync(0xffffffffu, rs1, o2);
        }
        l0 = l0 * al0 + rs0;
        l1 = l1 * al1 + rs1;
#pragma unroll
        for (int dn = 0; dn < 8; dn++) {
            oacc[dn][0] *= al0; oacc[dn][1] *= al0;
            oacc[dn][2] *= al1; oacc[dn][3] *= al1;
        }
        __syncwarp();   // P stores visible within warp before A-frag reads

        // ---- O += P V  (P scalar loads CF at stride 68; V scalar CF)
#pragma unroll
        for (int kt = 0; kt < 8; kt++) {
            uint32_t pa[4];
            pa[0] = __float_as_uint(Ps[(pr + g)     * PSTR + kt * 8 + tig]);
            pa[1] = __float_as_uint(Ps[(pr + 8 + g) * PSTR + kt * 8 + tig]);
            pa[2] = __float_as_uint(Ps[(pr + g)     * PSTR + kt * 8 + tig + 4]);
            pa[3] = __float_as_uint(Ps[(pr + 8 + g) * PSTR + kt * 8 + tig + 4]);
#pragma unroll
            for (int dn = 0; dn < 8; dn++) {
                uint32_t vb[2];
                vb[0] = __float_as_uint(Vs[(kt * 8 + tig)     * VSTR + dn * 8 + g]);
                vb[1] = __float_as_uint(Vs[(kt * 8 + tig + 4) * VSTR + dn * 8 + g]);
                mma_tf32(oacc[dn], pa, vb);
            }
        }
        __syncthreads();                     // all warps done with stage nt&1
        if (nt + 2 < NT) issue_tile(nt + 2);
        CP_COMMIT();
    }

    // ---- write context: exact to d_out; rounded+K-permuted copy for proj GEMM
    float inv0 = 1.0f / l0, inv1 = 1.0f / l1;
    int r0 = b * SEQ + q0 + wid * 16 + g;
    const int s0 = perm8(2 * tig), s1 = perm8(2 * tig + 1);
#pragma unroll
    for (int dn = 0; dn < 8; dn++) {
        int col = h * DH + dn * 8 + 2 * tig;
        int base8 = col - 2 * tig;
        float2 v0 = {oacc[dn][0] * inv0, oacc[dn][1] * inv0};
        float2 v1 = {oacc[dn][2] * inv1, oacc[dn][3] * inv1};
        *reinterpret_cast<float2*>(ctx + (size_t)r0 * HID + col)       = v0;
        *reinterpret_cast<float2*>(ctx + (size_t)(r0 + 8) * HID + col) = v1;
        ctxr[(size_t)r0 * HID + base8 + s0]       = f2tff(v0.x);
        ctxr[(size_t)r0 * HID + base8 + s1]       = f2tff(v0.y);
        ctxr[(size_t)(r0 + 8) * HID + base8 + s0] = f2tff(v1.x);
        ctxr[(size_t)(r0 + 8) * HID + base8 + s1] = f2tff(v1.y);
    }
}

// ===========================================================================
// Host side
// ===========================================================================
extern "C" void kernel_launch(void* const* d_in, const int* in_sizes, int n_in,
                              void* d_out, int out_size)
{
    const float* input = (const float*)d_in[0];
    const float* mask  = (const float*)d_in[1];
    const float* nw    = (const float*)d_in[2];
    const float* nb    = (const float*)d_in[3];
    const float* qkvw  = (const float*)d_in[4];
    const float* qkvb  = (const float*)d_in[5];
    const float* ow    = (const float*)d_in[6];

    float* out   = (float*)d_out;
    float* out_o = out;
    float* out_k = out + (size_t)TOK * HID;
    float* out_v = out + 2 * (size_t)TOK * HID;
    float* out_c = out + 3 * (size_t)TOK * HID;

    float *gq, *gln, *gkr, *gvr, *gcr, *gwq, *gwo;
    cudaGetSymbolAddress((void**)&gq,  g_q);
    cudaGetSymbolAddress((void**)&gln, g_ln);
    cudaGetSymbolAddress((void**)&gkr, g_kr);
    cudaGetSymbolAddress((void**)&gvr, g_vr);
    cudaGetSymbolAddress((void**)&gcr, g_cr);
    cudaGetSymbolAddress((void**)&gwq, g_wq);
    cudaGetSymbolAddress((void**)&gwo, g_wo);

    cudaFuncSetAttribute(gemm_mma<0>, cudaFuncAttributeMaxDynamicSharedMemorySize, GEMM_SMEM);
    cudaFuncSetAttribute(gemm_mma<1>, cudaFuncAttributeMaxDynamicSharedMemorySize, GEMM_SMEM);
    cudaFuncSetAttribute(attn_mma,    cudaFuncAttributeMaxDynamicSharedMemorySize, ATT_SMEM);

    round4_kernel<<<(3*HID*HID/4 + 255)/256, 256>>>(qkvw, gwq, 3*HID*HID/4);
    round4_kernel<<<(HID*HID/4 + 255)/256, 256>>>(ow, gwo, HID*HID/4);
    ln_kernel<<<TOK, 256>>>(input, nw, nb, gln);
    gemm_mma<0><<<dim3(TOK/128, 3*HID/128), 256, GEMM_SMEM>>>(
        gln, gwq, qkvb, gq, out_k, gkr, out_v, gvr, nullptr);
    attn_mma<<<dim3(SEQ/128, NHD, BSZ), 256, ATT_SMEM>>>(gq, gkr, gvr, mask, out_c, gcr);
    gemm_mma<1><<<dim3(TOK/128, HID/128), 256, GEMM_SMEM>>>(
        gcr, gwo, nullptr, nullptr, nullptr, nullptr, nullptr, nullptr, out_o);
}

// round 10
// speedup vs baseline: 2.1678x; 1.9159x over previous
#include <cuda_runtime.h>
#include <cuda_fp16.h>
#include <math.h>
#include <stdint.h>

#define BSZ 4
#define SEQ 2048
#define HID 1024
#define NHD 16
#define DH  64
#define TOK (BSZ*SEQ)   // 8192

// Scratch: fp16 operands (pre-rounded). g_ln/g_wq/g_wo/g_cr/g_q/g_kr are
// K-dim permuted in 16-groups: slots 4t+{0,1,2,3} = cols {2t,2t+1,2t+8,2t+9}.
// g_vr is plain row-major fp16 (ldmatrix.trans handles its fragments).
__device__ __half g_q  [(size_t)TOK*HID];
__device__ __half g_ln [(size_t)TOK*HID];
__device__ __half g_kr [(size_t)TOK*HID];
__device__ __half g_vr [(size_t)TOK*HID];
__device__ __half g_cr [(size_t)TOK*HID];
__device__ __half g_wq [(size_t)3*HID*HID];
__device__ __half g_wo [(size_t)HID*HID];

// ===========================================================================
// helpers
// ===========================================================================
__device__ __forceinline__ uint32_t s2u(const void* p) {
    uint32_t a;
    asm("{ .reg .u64 t; cvta.to.shared.u64 t, %1; cvt.u32.u64 %0, t; }"
        : "=r"(a) : "l"(p));
    return a;
}
// pack {lo, hi} floats -> f16x2 (b32)
__device__ __forceinline__ uint32_t h2(float hi, float lo) {
    uint32_t r;
    asm("cvt.rn.f16x2.f32 %0, %1, %2;" : "=r"(r) : "f"(hi), "f"(lo));
    return r;
}
// col (0..15) -> permuted slot
__device__ __forceinline__ int perm16(int c) {
    return 4 * ((c & 7) >> 1) + ((c & 8) >> 2) + (c & 1);
}
// D += A*B, m16n8k16 f16 (f32 accum)
__device__ __forceinline__ void mma_f16(float* d, const uint32_t* a, const uint32_t* b) {
    asm volatile(
        "mma.sync.aligned.m16n8k16.row.col.f32.f16.f16.f32 "
        "{%0,%1,%2,%3}, {%4,%5,%6,%7}, {%8,%9}, {%0,%1,%2,%3};"
        : "+f"(d[0]), "+f"(d[1]), "+f"(d[2]), "+f"(d[3])
        : "r"(a[0]), "r"(a[1]), "r"(a[2]), "r"(a[3]), "r"(b[0]), "r"(b[1]));
}
__device__ __forceinline__ void ldsm4t(uint32_t& r0, uint32_t& r1,
                                       uint32_t& r2, uint32_t& r3, uint32_t a) {
    asm volatile("ldmatrix.sync.aligned.m8n8.x4.trans.shared.b16 {%0,%1,%2,%3}, [%4];"
                 : "=r"(r0), "=r"(r1), "=r"(r2), "=r"(r3) : "r"(a));
}
#define CP_ASYNC16(dst, src) \
    asm volatile("cp.async.cg.shared.global [%0], [%1], 16;" :: "r"(dst), "l"(src))
#define CP_COMMIT() asm volatile("cp.async.commit_group;" ::: "memory")
#define CP_WAIT(n)  asm volatile("cp.async.wait_group %0;" :: "n"(n) : "memory")

// ===========================================================================
// Kernel 0: round f32 -> fp16 with 16-group K-permutation
// ===========================================================================
__global__ __launch_bounds__(256) void round16_kernel(const float* __restrict__ src,
                                                      __half* __restrict__ dst, int n4)
{
    int i = blockIdx.x * blockDim.x + threadIdx.x;
    if (i < n4) {
        float4 v = reinterpret_cast<const float4*>(src)[i];
        int cb = i * 4;
        int base = cb & ~15;
        int c0 = cb & 15;                       // 0,4,8,12
        int s = 4 * ((c0 & 7) >> 1) + ((c0 & 8) >> 2);
        *reinterpret_cast<uint32_t*>(dst + base + s)     = h2(v.y, v.x);
        *reinterpret_cast<uint32_t*>(dst + base + s + 4) = h2(v.w, v.z);
    }
}

// ===========================================================================
// Kernel 1: LayerNorm -> g_ln (fp16, K-permuted)
// ===========================================================================
__global__ __launch_bounds__(256) void ln_kernel(const float* __restrict__ x,
                                                 const float* __restrict__ w,
                                                 const float* __restrict__ bb,
                                                 __half* __restrict__ y)
{
    int row = blockIdx.x;
    int t = threadIdx.x;
    float4 v = reinterpret_cast<const float4*>(x + (size_t)row * HID)[t];
    float s = v.x + v.y + v.z + v.w;
    float q = v.x*v.x + v.y*v.y + v.z*v.z + v.w*v.w;
#pragma unroll
    for (int o = 16; o > 0; o >>= 1) {
        s += __shfl_xor_sync(0xffffffffu, s, o);
        q += __shfl_xor_sync(0xffffffffu, q, o);
    }
    __shared__ float ss[8], sq[8], smu, srs;
    if ((t & 31) == 0) { ss[t >> 5] = s; sq[t >> 5] = q; }
    __syncthreads();
    if (t == 0) {
        float S = 0.f, Q2 = 0.f;
#pragma unroll
        for (int i = 0; i < 8; i++) { S += ss[i]; Q2 += sq[i]; }
        float mu = S * (1.0f / HID);
        smu = mu;
        srs = rsqrtf(Q2 * (1.0f / HID) - mu * mu + 1e-12f);
    }
    __syncthreads();
    float mu = smu, rs = srs;
    float4 w4 = reinterpret_cast<const float4*>(w)[t];
    float4 b4 = reinterpret_cast<const float4*>(bb)[t];
    float o0 = (v.x - mu) * rs * w4.x + b4.x;
    float o1 = (v.y - mu) * rs * w4.y + b4.y;
    float o2 = (v.z - mu) * rs * w4.z + b4.z;
    float o3 = (v.w - mu) * rs * w4.w + b4.w;
    int cb = 4 * t, base = cb & ~15, c0 = cb & 15;
    int sl = 4 * ((c0 & 7) >> 1) + ((c0 & 8) >> 2);
    __half* yr = y + (size_t)row * HID + base;
    *reinterpret_cast<uint32_t*>(yr + sl)     = h2(o1, o0);
    *reinterpret_cast<uint32_t*>(yr + sl + 4) = h2(o3, o2);
}

// ===========================================================================
// Kernel 2/4: fp16 mma GEMM  C[M,N] = A[M,K] * W[N,K]^T  (A,W fp16 perm16)
//   128x128 CTA, 256 thr, 8 warps (4M x 2N), warp 32x64.
//   BK=64 halves, 2-stage cp.async, row stride 80 halves (40w = 8 mod 32: CF).
// ===========================================================================
#define GSTRH 80
#define GTILEH (128*GSTRH)          // 10240 halves / tile
#define GSSH   (2*GTILEH)           // 20480 halves / stage
#define GEMM_SMEM (2*GSSH*2)        // 81920 B -> 2 CTAs/SM

template<int MODE>
__global__ __launch_bounds__(256, 2) void gemm_mma(
    const __half* __restrict__ Ap, const __half* __restrict__ W,
    const float* __restrict__ bias,
    __half* __restrict__ outq,
    float* __restrict__ outk, __half* __restrict__ outkr,
    float* __restrict__ outv, __half* __restrict__ outvr,
    float* __restrict__ outp)
{
    extern __shared__ __half smh[];
    const uint32_t smb = s2u(smh);

    const int tid = threadIdx.x;
    const int wid = tid >> 5, lane = tid & 31;
    const int g = lane >> 2, tig = lane & 3;
    const int wM = wid & 3, wN = wid >> 2;
    const int m0 = blockIdx.x * 128, n0 = blockIdx.y * 128;
    const int NT = HID / 64;   // 16

    float acc[2][8][4];
#pragma unroll
    for (int a = 0; a < 2; a++)
#pragma unroll
        for (int b = 0; b < 8; b++)
#pragma unroll
            for (int c = 0; c < 4; c++) acc[a][b][c] = 0.f;

    // hoisted loader pointers: 8 chunks/thread (A:4, B:4)
    const __half* pS[8];
    uint32_t dS[8];
    {
        int row = tid >> 3, c = tid & 7;
#pragma unroll
        for (int j = 0; j < 4; j++) {
            pS[j]     = Ap + (size_t)(m0 + row + 32*j) * HID + c * 8;
            dS[j]     = (uint32_t)((row + 32*j) * GSTRH + c * 8);
            pS[j + 4] = W  + (size_t)(n0 + row + 32*j) * HID + c * 8;
            dS[j + 4] = (uint32_t)(GTILEH + (row + 32*j) * GSTRH + c * 8);
        }
    }
    auto load_stage = [&](int s, int kt) {
        uint32_t base = smb + (uint32_t)s * GSSH * 2;
#pragma unroll
        for (int j = 0; j < 8; j++)
            CP_ASYNC16(base + dS[j] * 2, pS[j] + kt * 64);
    };

    load_stage(0, 0); CP_COMMIT();
    load_stage(1, 1); CP_COMMIT();

    for (int kt = 0; kt < NT; kt++) {
        CP_WAIT(1);
        __syncthreads();
        const __half* As = smh + (kt & 1) * GSSH;
        const __half* Bs = As + GTILEH;
#pragma unroll
        for (int ks = 0; ks < 4; ks++) {
            const int wA = ks * 16 + 4 * tig;
            uint32_t af[2][4], bf[8][2];
#pragma unroll
            for (int mt = 0; mt < 2; mt++) {
                int r = wM * 32 + mt * 16 + g;
                uint2 v0 = *reinterpret_cast<const uint2*>(As + r * GSTRH + wA);
                uint2 v1 = *reinterpret_cast<const uint2*>(As + (r + 8) * GSTRH + wA);
                af[mt][0] = v0.x; af[mt][1] = v1.x; af[mt][2] = v0.y; af[mt][3] = v1.y;
            }
#pragma unroll
            for (int nt = 0; nt < 8; nt++) {
                int n = wN * 64 + nt * 8 + g;
                uint2 v = *reinterpret_cast<const uint2*>(Bs + n * GSTRH + wA);
                bf[nt][0] = v.x; bf[nt][1] = v.y;
            }
#pragma unroll
            for (int mt = 0; mt < 2; mt++)
#pragma unroll
                for (int nt = 0; nt < 8; nt++)
                    mma_f16(acc[mt][nt], af[mt], bf[nt]);
        }
        __syncthreads();
        if (kt + 2 < NT) load_stage(kt & 1, kt + 2);
        CP_COMMIT();
    }

    // ---- epilogue
#pragma unroll
    for (int nt = 0; nt < 8; nt++) {
        int cb = n0 + wN * 64 + nt * 8 + 2 * tig;
        float2 bv = {0.f, 0.f};
        int seg = 0, col = cb;
        if (MODE == 0) {
            bv = *reinterpret_cast<const float2*>(bias + cb);
            seg = cb >> 10;
            col = cb & 1023;
        }
        int grp = col & ~15;
        int sl  = grp + perm16(col & 15);     // even slot, pair adjacent
#pragma unroll
        for (int mt = 0; mt < 2; mt++) {
            int r = m0 + wM * 32 + mt * 16 + g;
#pragma unroll
            for (int hh = 0; hh < 2; hh++) {
                size_t roff = (size_t)(r + hh * 8) * HID;
                float2 v = {acc[mt][nt][2*hh+0] + bv.x, acc[mt][nt][2*hh+1] + bv.y};
                if (MODE == 0) {
                    uint32_t u = h2(v.y, v.x);
                    if (seg == 0) {
                        *reinterpret_cast<uint32_t*>(outq + roff + sl) = u;
                    } else if (seg == 1) {
                        *reinterpret_cast<float2*>(outk + roff + col) = v;
                        *reinterpret_cast<uint32_t*>(outkr + roff + sl) = u;
                    } else {
                        *reinterpret_cast<float2*>(outv + roff + col) = v;
                        *reinterpret_cast<uint32_t*>(outvr + roff + col) = u;  // no perm
                    }
                } else {
                    *reinterpret_cast<float2*>(outp + roff + col) = v;
                }
            }
        }
    }
}

// ===========================================================================
// Kernel 3: flash attention, fp16 mma, 2-stage cp.async KV pipeline.
//   Q/K fp16 perm16 along d -> LDS.64 frags; V fp16 row-major -> ldmatrix.trans.
//   P lives in registers (S C-frag == O A-frag layout). No P smem.
//   stage (halves): K[64][80] | V[64][72] ; mask f32 at byte 19456.
// ===========================================================================
#define AKSTR 80
#define AVSTR 72
#define AVOFF (64*AKSTR)                    // 5120 halves
#define ASTG_B 19712                        // stage bytes (19456 + 256 mask)
#define ATT_SMEM (2*ASTG_B)                 // 39424 B

__global__ __launch_bounds__(256) void attn_mma(
    const __half* __restrict__ Qp, const __half* __restrict__ Kp,
    const __half* __restrict__ Vp, const float* __restrict__ mask,
    float* __restrict__ ctx, __half* __restrict__ ctxr)
{
    extern __shared__ __half smh[];
    const uint32_t smb = s2u(smh);

    const int tid = threadIdx.x;
    const int wid = tid >> 5, lane = tid & 31;
    const int g = lane >> 2, tig = lane & 3;
    const int q0 = blockIdx.x * 128;
    const int h  = blockIdx.y;
    const int b  = blockIdx.z;
    const int NT = SEQ / 64;   // 32
    const int pr = wid * 16;

    const __half* qbase = Qp + (size_t)b * SEQ * HID + h * DH;
    const __half* kbase = Kp + (size_t)b * SEQ * HID + h * DH;
    const __half* vbase = Vp + (size_t)b * SEQ * HID + h * DH;
    const float*  maskb = mask + (size_t)b * SEQ;

    const float L2E = 1.4426950408889634f;
    const float SCL = 0.125f * L2E;

    // hoisted KV loader pointers: K 2 chunks, V 2 chunks / thread + mask
    const __half* pK[2]; const __half* pV[2];
    uint32_t dK[2], dV[2];
    {
        int row = tid >> 3, c = tid & 7;
#pragma unroll
        for (int j = 0; j < 2; j++) {
            pK[j] = kbase + (size_t)(row + 32*j) * HID + c * 8;
            dK[j] = (uint32_t)((row + 32*j) * AKSTR + c * 8);
            pV[j] = vbase + (size_t)(row + 32*j) * HID + c * 8;
            dV[j] = (uint32_t)(AVOFF + (row + 32*j) * AVSTR + c * 8);
        }
    }
    const size_t KADV = (size_t)64 * HID;
    auto issue_tile = [&](int nt) {
        uint32_t base = smb + (uint32_t)(nt & 1) * ASTG_B;
#pragma unroll
        for (int j = 0; j < 2; j++) {
            CP_ASYNC16(base + dK[j] * 2, pK[j] + nt * KADV);
            CP_ASYNC16(base + dV[j] * 2, pV[j] + nt * KADV);
        }
        if (tid < 16)
            CP_ASYNC16(base + 19456 + tid * 16, maskb + nt * 64 + tid * 4);
    };

    issue_tile(0); CP_COMMIT();
    issue_tile(1); CP_COMMIT();

    // ---- Q fragments straight from global (perm16 along d)
    uint32_t qf[4][4];
    {
        const __half* q0p = qbase + (size_t)(q0 + pr + g) * HID;
        const __half* q1p = q0p + (size_t)8 * HID;
#pragma unroll
        for (int j = 0; j < 4; j++) {
            uint2 u0 = *reinterpret_cast<const uint2*>(q0p + j * 16 + 4 * tig);
            uint2 u1 = *reinterpret_cast<const uint2*>(q1p + j * 16 + 4 * tig);
            qf[j][0] = u0.x; qf[j][1] = u1.x; qf[j][2] = u0.y; qf[j][3] = u1.y;
        }
    }

    // ldmatrix per-thread address components
    const int rbase = (lane & 7) + 8 * ((lane >> 3) & 1);
    const int cbase = 8 * (lane >> 4);

    float m0r = -1e30f, m1r = -1e30f, l0 = 0.f, l1 = 0.f;
    float oacc[8][4];
#pragma unroll
    for (int i = 0; i < 8; i++)
#pragma unroll
        for (int j = 0; j < 4; j++) oacc[i][j] = 0.f;

    for (int nt = 0; nt < NT; nt++) {
        CP_WAIT(1);
        __syncthreads();
        const __half* Ks = smh + (nt & 1) * (ASTG_B / 2);
        const __half* Vs = Ks + AVOFF;
        const float*  Ms = reinterpret_cast<const float*>(
            reinterpret_cast<const char*>(Ks) + 19456);
        const uint32_t vsb = smb + (uint32_t)(nt & 1) * ASTG_B + AVOFF * 2;

        // ---- S = Q K^T
        float sf[8][4];
#pragma unroll
        for (int i = 0; i < 8; i++)
#pragma unroll
            for (int j = 0; j < 4; j++) sf[i][j] = 0.f;
#pragma unroll
        for (int ks = 0; ks < 4; ks++) {
            const int wK = ks * 16 + 4 * tig;
#pragma unroll
            for (int sn = 0; sn < 8; sn++) {
                uint2 v = *reinterpret_cast<const uint2*>(Ks + (sn * 8 + g) * AKSTR + wK);
                uint32_t kb[2] = {v.x, v.y};
                mma_f16(sf[sn], qf[ks], kb);
            }
        }

        // ---- online softmax (base-2 domain)
        float zmax0 = -1e30f, zmax1 = -1e30f;
#pragma unroll
        for (int sn = 0; sn < 8; sn++) {
            float mc0 = Ms[sn * 8 + 2 * tig]     * L2E;
            float mc1 = Ms[sn * 8 + 2 * tig + 1] * L2E;
            sf[sn][0] = sf[sn][0] * SCL + mc0;
            sf[sn][1] = sf[sn][1] * SCL + mc1;
            sf[sn][2] = sf[sn][2] * SCL + mc0;
            sf[sn][3] = sf[sn][3] * SCL + mc1;
            zmax0 = fmaxf(zmax0, fmaxf(sf[sn][0], sf[sn][1]));
            zmax1 = fmaxf(zmax1, fmaxf(sf[sn][2], sf[sn][3]));
        }
#pragma unroll
        for (int o2 = 1; o2 < 4; o2 <<= 1) {
            zmax0 = fmaxf(zmax0, __shfl_xor_sync(0xffffffffu, zmax0, o2));
            zmax1 = fmaxf(zmax1, __shfl_xor_sync(0xffffffffu, zmax1, o2));
        }
        float mn0 = fmaxf(m0r, zmax0), mn1 = fmaxf(m1r, zmax1);
        float al0 = exp2f(m0r - mn0), al1 = exp2f(m1r - mn1);
        m0r = mn0; m1r = mn1;

        float rs0 = 0.f, rs1 = 0.f;
#pragma unroll
        for (int sn = 0; sn < 8; sn++) {
            sf[sn][0] = exp2f(sf[sn][0] - mn0);
            sf[sn][1] = exp2f(sf[sn][1] - mn0);
            sf[sn][2] = exp2f(sf[sn][2] - mn1);
            sf[sn][3] = exp2f(sf[sn][3] - mn1);
            rs0 += sf[sn][0] + sf[sn][1];
            rs1 += sf[sn][2] + sf[sn][3];
        }
#pragma unroll
        for (int o2 = 1; o2 < 4; o2 <<= 1) {
            rs0 += __shfl_xor_sync(0xffffffffu, rs0, o2);
            rs1 += __shfl_xor_sync(0xffffffffu, rs1, o2);
        }
        l0 = l0 * al0 + rs0;
        l1 = l1 * al1 + rs1;
#pragma unroll
        for (int dn = 0; dn < 8; dn++) {
            oacc[dn][0] *= al0; oacc[dn][1] *= al0;
            oacc[dn][2] *= al1; oacc[dn][3] *= al1;
        }

        // ---- O += P V  (P from registers; V via ldmatrix.trans)
#pragma unroll
        for (int j = 0; j < 4; j++) {
            uint32_t pa[4];
            pa[0] = h2(sf[2*j][1],   sf[2*j][0]);
            pa[1] = h2(sf[2*j][3],   sf[2*j][2]);
            pa[2] = h2(sf[2*j+1][1], sf[2*j+1][0]);
            pa[3] = h2(sf[2*j+1][3], sf[2*j+1][2]);
            uint32_t rowa = vsb + (uint32_t)((16*j + rbase) * AVSTR + cbase) * 2;
#pragma unroll
            for (int dnp = 0; dnp < 4; dnp++) {
                uint32_t v0, v1, v2, v3;
                ldsm4t(v0, v1, v2, v3, rowa + (uint32_t)(dnp * 16) * 2);
                uint32_t vb0[2] = {v0, v1};
                uint32_t vb1[2] = {v2, v3};
                mma_f16(oacc[2*dnp],     pa, vb0);
                mma_f16(oacc[2*dnp + 1], pa, vb1);
            }
        }
        __syncthreads();
        if (nt + 2 < NT) issue_tile(nt + 2);
        CP_COMMIT();
    }

    // ---- write context: exact f32 to d_out; fp16 perm16 copy for proj GEMM
    float inv0 = 1.0f / l0, inv1 = 1.0f / l1;
    int r0 = b * SEQ + q0 + pr + g;
#pragma unroll
    for (int dn = 0; dn < 8; dn++) {
        int col = h * DH + dn * 8 + 2 * tig;
        int sl = (col & ~15) + perm16(col & 15);
        float2 v0 = {oacc[dn][0] * inv0, oacc[dn][1] * inv0};
        float2 v1 = {oacc[dn][2] * inv1, oacc[dn][3] * inv1};
        *reinterpret_cast<float2*>(ctx + (size_t)r0 * HID + col)       = v0;
        *reinterpret_cast<float2*>(ctx + (size_t)(r0 + 8) * HID + col) = v1;
        *reinterpret_cast<uint32_t*>(ctxr + (size_t)r0 * HID + sl)       = h2(v0.y, v0.x);
        *reinterpret_cast<uint32_t*>(ctxr + (size_t)(r0 + 8) * HID + sl) = h2(v1.y, v1.x);
    }
}

// ===========================================================================
// Host side
// ===========================================================================
extern "C" void kernel_launch(void* const* d_in, const int* in_sizes, int n_in,
                              void* d_out, int out_size)
{
    const float* input = (const float*)d_in[0];
    const float* mask  = (const float*)d_in[1];
    const float* nw    = (const float*)d_in[2];
    const float* nb    = (const float*)d_in[3];
    const float* qkvw  = (const float*)d_in[4];
    const float* qkvb  = (const float*)d_in[5];
    const float* ow    = (const float*)d_in[6];

    float* out   = (float*)d_out;
    float* out_o = out;
    float* out_k = out + (size_t)TOK * HID;
    float* out_v = out + 2 * (size_t)TOK * HID;
    float* out_c = out + 3 * (size_t)TOK * HID;

    __half *gq, *gln, *gkr, *gvr, *gcr, *gwq, *gwo;
    cudaGetSymbolAddress((void**)&gq,  g_q);
    cudaGetSymbolAddress((void**)&gln, g_ln);
    cudaGetSymbolAddress((void**)&gkr, g_kr);
    cudaGetSymbolAddress((void**)&gvr, g_vr);
    cudaGetSymbolAddress((void**)&gcr, g_cr);
    cudaGetSymbolAddress((void**)&gwq, g_wq);
    cudaGetSymbolAddress((void**)&gwo, g_wo);

    cudaFuncSetAttribute(gemm_mma<0>, cudaFuncAttributeMaxDynamicSharedMemorySize, GEMM_SMEM);
    cudaFuncSetAttribute(gemm_mma<1>, cudaFuncAttributeMaxDynamicSharedMemorySize, GEMM_SMEM);
    cudaFuncSetAttribute(attn_mma,    cudaFuncAttributeMaxDynamicSharedMemorySize, ATT_SMEM);

    round16_kernel<<<(3*HID*HID/4 + 255)/256, 256>>>(qkvw, gwq, 3*HID*HID/4);
    round16_kernel<<<(HID*HID/4 + 255)/256, 256>>>(ow, gwo, HID*HID/4);
    ln_kernel<<<TOK, 256>>>(input, nw, nb, gln);
    gemm_mma<0><<<dim3(TOK/128, 3*HID/128), 256, GEMM_SMEM>>>(
        gln, gwq, qkvb, gq, out_k, gkr, out_v, gvr, nullptr);
    attn_mma<<<dim3(SEQ/128, NHD, BSZ), 256, ATT_SMEM>>>(gq, gkr, gvr, mask, out_c, gcr);
    gemm_mma<1><<<dim3(TOK/128, HID/128), 256, GEMM_SMEM>>>(
        gcr, gwo, nullptr, nullptr, nullptr, nullptr, nullptr, nullptr, out_o);
}